// round 3
// baseline (speedup 1.0000x reference)
#include <cuda_runtime.h>
#include <math.h>

// Problem constants (from reference)
#define BB 256
#define GG 2048
#define FF 128
#define RR 512
#define KK 128          // top-k == F
#define NTHREADS 1024
#define TILE_STRIDE 129 // padded row stride for conflict-free transposed reads

struct SmemT {
    float h[RR];               // h_t row
    float scorer[FF];          // normalized scorer
    float tanhv[KK];           // tanh of top-k vals
    float val[GG];             // scores (sorted in place)
    int   idx[GG];             // indices (sorted in place)
    float red[NTHREADS];       // reduction scratch
    float tile[KK * TILE_STRIDE]; // gathered 128x128 tile (padded)
};

__device__ __forceinline__ bool pair_before(float v1, int i1, float v2, int i2) {
    // final order: descending value, ties -> ascending index (jax top_k)
    return (v1 > v2) || (v1 == v2 && i1 < i2);
}

__global__ void __launch_bounds__(NTHREADS, 1)
topk_fused_kernel(const float* __restrict__ emb,    // [B,G,F]
                  const float* __restrict__ mask,   // [B,G]
                  const float* __restrict__ h_t,    // [B,R]
                  const float* __restrict__ W,      // [R,F]
                  const float* __restrict__ bmap,   // [F]
                  float* __restrict__ out,          // [B,F,K]
                  float* __restrict__ pol)          // [B]
{
    extern __shared__ char raw[];
    SmemT* s = reinterpret_cast<SmemT*>(raw);

    const int tid  = threadIdx.x;
    const int b    = blockIdx.x;
    const int lane = tid & 31;
    const int w    = tid >> 5;

    const size_t emb_base = (size_t)b * GG * FF;

    // ---------------- 1. scorer = tanh(h_t[b] @ W + bmap), then / ||.|| ------
    if (tid < RR) s->h[tid] = h_t[(size_t)b * RR + tid];
    __syncthreads();

    {
        const int f  = tid & (FF - 1);
        const int gr = tid >> 7;          // 0..7, each covers 64 rows of R
        float part = 0.f;
        const int r0 = gr * 64;
        #pragma unroll 8
        for (int r = 0; r < 64; r++) {
            part += s->h[r0 + r] * W[(r0 + r) * FF + f];
        }
        s->red[tid] = part;
    }
    __syncthreads();

    if (tid < FF) {
        float acc = bmap[tid];
        #pragma unroll
        for (int gr = 0; gr < 8; gr++) acc += s->red[gr * FF + tid];
        float t = tanhf(acc);
        s->scorer[tid] = t;
        float sq = t * t;
        #pragma unroll
        for (int o = 16; o; o >>= 1) sq += __shfl_xor_sync(0xffffffffu, sq, o);
        if (lane == 0) s->red[w] = sq;   // warps 0..3
    }
    __syncthreads();
    if (tid == 0) {
        float n2 = s->red[0] + s->red[1] + s->red[2] + s->red[3];
        s->red[8] = 1.0f / sqrtf(n2);
    }
    __syncthreads();
    if (tid < FF) s->scorer[tid] *= s->red[8];
    __syncthreads();

    // ---------------- 2. scores[g] = emb[b,g,:] . scorer + mask --------------
    {
        float4 sc = *reinterpret_cast<const float4*>(&s->scorer[lane * 4]);
        const int g0 = w * 64;            // each warp: 64 consecutive rows
        #pragma unroll 4
        for (int i = 0; i < 64; i++) {
            const int g = g0 + i;
            float4 e = *reinterpret_cast<const float4*>(
                emb + emb_base + (size_t)g * FF + lane * 4);
            float d = e.x * sc.x + e.y * sc.y + e.z * sc.z + e.w * sc.w;
            #pragma unroll
            for (int o = 16; o; o >>= 1) d += __shfl_xor_sync(0xffffffffu, d, o);
            if (lane == 0) {
                s->val[g] = d + mask[(size_t)b * GG + g];
                s->idx[g] = g;
            }
        }
    }
    __syncthreads();

    // ---------------- 3. bitonic sort (descending val, ties asc idx) --------
    for (int k = 2; k <= GG; k <<= 1) {
        for (int j = k >> 1; j > 0; j >>= 1) {
            int i   = ((tid & ~(j - 1)) << 1) | (tid & (j - 1));
            int ixj = i | j;
            bool dir = ((i & k) == 0);
            float va = s->val[i];  int ia = s->idx[i];
            float vb = s->val[ixj]; int ib = s->idx[ixj];
            bool ab = pair_before(va, ia, vb, ib);
            if (dir ? !ab : ab) {
                s->val[i] = vb;  s->idx[i] = ib;
                s->val[ixj] = va; s->idx[ixj] = ia;
            }
            __syncthreads();
        }
    }

    // ---------------- 4. log-softmax denom + policy score --------------------
    const float vmax = s->val[0];   // sorted descending -> max is first
    {
        float le = expf(s->val[tid] - vmax) + expf(s->val[tid + NTHREADS] - vmax);
        s->red[tid] = le;
    }
    __syncthreads();
    for (int sft = NTHREADS / 2; sft > 0; sft >>= 1) {
        if (tid < sft) s->red[tid] += s->red[tid + sft];
        __syncthreads();
    }
    float lse_t0 = (tid == 0) ? logf(s->red[0]) : 0.f;

    float tp = (tid < KK) ? s->val[tid] : 0.f;
    if (tid < KK) {
        #pragma unroll
        for (int o = 16; o; o >>= 1) tp += __shfl_xor_sync(0xffffffffu, tp, o);
        s->tanhv[tid] = tanhf(s->val[tid]);
    }
    __syncthreads();               // lse read done before red overwrite
    if (tid < KK && lane == 0) s->red[w] = tp;  // warps 0..3
    __syncthreads();
    if (tid == 0) {
        float topsum = s->red[0] + s->red[1] + s->red[2] + s->red[3];
        pol[b] = topsum * (1.0f / KK) - vmax - lse_t0;
    }

    // ---------------- 5. gather top-k rows into padded tile ------------------
    {
        #pragma unroll
        for (int rr = 0; rr < 4; rr++) {
            const int k  = w * 4 + rr;
            const int row = s->idx[k];
            float4 e = *reinterpret_cast<const float4*>(
                emb + emb_base + (size_t)row * FF + lane * 4);
            float* tp2 = &s->tile[k * TILE_STRIDE + lane * 4];
            tp2[0] = e.x; tp2[1] = e.y; tp2[2] = e.z; tp2[3] = e.w;
        }
    }
    __syncthreads();

    // ---------------- 6. transposed, scaled write: out[b,f,k] ----------------
    {
        const int k  = tid & (KK - 1);
        const int f0 = tid >> 7;          // 0..7
        const float tv = s->tanhv[k];
        float* ob = out + (size_t)b * FF * KK;
        #pragma unroll
        for (int f = f0; f < FF; f += 8) {
            ob[f * KK + k] = s->tile[k * TILE_STRIDE + f] * tv;
        }
    }
}

extern "C" void kernel_launch(void* const* d_in, const int* in_sizes, int n_in,
                              void* d_out, int out_size) {
    const float* emb  = (const float*)d_in[0]; // node_embs [B,G,F]
    const float* mask = (const float*)d_in[1]; // [B,G]
    const float* h_t  = (const float*)d_in[2]; // [B,R]
    const float* W    = (const float*)d_in[3]; // [R,F]
    const float* bmap = (const float*)d_in[4]; // [F]

    float* out = (float*)d_out;                 // [B,F,K] then [B]
    float* pol = out + (size_t)BB * FF * KK;

    const size_t smem = sizeof(SmemT);
    cudaFuncSetAttribute(topk_fused_kernel,
                         cudaFuncAttributeMaxDynamicSharedMemorySize, (int)smem);

    topk_fused_kernel<<<BB, NTHREADS, smem>>>(emb, mask, h_t, W, bmap, out, pol);
}